// round 1
// baseline (speedup 1.0000x reference)
#include <cuda_runtime.h>
#include <cstdint>
#include <cstdio>

#define NB   2
#define NN   50000
#define HH   64
#define NE   1000000
#define NOBS 128
#define NA   18
#define NAFF 512
#define NEFF 256

// ---------------- device scratch (no allocations allowed) ----------------
__device__ float g_agg[NB * NN * HH];     // 25.6 MB aggregated messages (pre-W_msg)
__device__ float g_Wp[128 * 128];         // fused weight: rows 0..63 = s part, 64..127 = agg part
                                          // cols 0..63 = z-pre, 64..127 = cand-pre
__device__ float g_projG[NB * HH];        // injected @ Wg_bot
__device__ float g_projC[NB * HH];        // injected @ Wc_bot
__device__ int   g_flag[NN];              // 1 if node is afferent

// ---------------- K1a: projections + flags ----------------
__global__ void prep_small_kernel(const float* __restrict__ obs,
                                  const float* __restrict__ W_in,
                                  const float* __restrict__ b_in,
                                  const float* __restrict__ W_gate,
                                  const float* __restrict__ W_cand,
                                  const int* __restrict__ afferent_idx) {
    __shared__ float proj[NB * HH];
    int t = threadIdx.x;            // 128 threads
    int b = t >> 6, h = t & 63;
    // projected = obs @ W_in + b_in
    float acc = b_in[h];
    for (int o = 0; o < NOBS; o++)
        acc += obs[b * NOBS + o] * W_in[o * HH + h];
    proj[b * HH + h] = acc;
    __syncthreads();
    // projG/projC = projected @ W_{gate,cand}[64:,:]
    float ag = 0.f, ac = 0.f;
    for (int k = 0; k < HH; k++) {
        float p = proj[b * HH + k];
        ag += p * W_gate[(HH + k) * HH + h];
        ac += p * W_cand[(HH + k) * HH + h];
    }
    g_projG[b * HH + h] = ag;
    g_projC[b * HH + h] = ac;
    // scatter afferent flags (g_flag pre-zeroed by memset)
    for (int i = t; i < NAFF; i += 128)
        g_flag[afferent_idx[i]] = 1;
}

// ---------------- K1b: fused weight W' ----------------
__global__ void prep_W_kernel(const float* __restrict__ W_msg,
                              const float* __restrict__ W_gate,
                              const float* __restrict__ W_cand) {
    int c = blockIdx.x;     // output column 0..127
    int k = threadIdx.x;    // input row 0..127
    float w;
    if (k < HH) {
        w = (c < HH) ? W_gate[k * HH + c] : W_cand[k * HH + (c - HH)];
    } else {
        int km = k - HH;
        float acc = 0.f;
        if (c < HH) {
            for (int t = 0; t < HH; t++)
                acc += W_msg[km * HH + t] * W_gate[(HH + t) * HH + c];
        } else {
            for (int t = 0; t < HH; t++)
                acc += W_msg[km * HH + t] * W_cand[(HH + t) * HH + (c - HH)];
        }
        w = acc;
    }
    g_Wp[k * 128 + c] = w;
}

// ---------------- K2: edge aggregation (one warp per edge) ----------------
__global__ void __launch_bounds__(256) edge_kernel(const float* __restrict__ state,
                                                   const int* __restrict__ src_index,
                                                   const int* __restrict__ dst_index) {
    int e = blockIdx.x * 8 + (threadIdx.x >> 5);
    if (e >= NE) return;
    int lane = threadIdx.x & 31;
    int src = __ldg(src_index + e);
    int dst = __ldg(dst_index + e);
    int b = lane >> 4;          // 0..1
    int p = lane & 15;          // float4 index within the 64-float row
    const float4* srow = reinterpret_cast<const float4*>(state) + ((size_t)b * NN + src) * 16 + p;
    float4 v = __ldg(srow);
    float* d = g_agg + ((size_t)b * NN + dst) * HH + p * 4;
    asm volatile("red.global.add.v4.f32 [%0], {%1,%2,%3,%4};"
                 :: "l"(d), "f"(v.x), "f"(v.y), "f"(v.z), "f"(v.w)
                 : "memory");
}

// ---------------- K3: fused GEMM + GRU epilogue ----------------
// X = [s | agg] (100K x 128)  @  W' (128 x 128) ; epilogue: sigmoid/tanh blend.
// One warp handles one node (both batches). Lane j owns output cols 4j..4j+3.
__global__ void __launch_bounds__(256) gemm_kernel(const float* __restrict__ state,
                                                   const float* __restrict__ b_gate,
                                                   const float* __restrict__ b_cand,
                                                   float* __restrict__ out_ns) {
    extern __shared__ float smem[];
    float* Ws = smem;                 // 128*128
    float* xs = Ws + 128 * 128;       // 8 warps * 256 floats: [warp][b][128]
    float* bg = xs + 8 * 256;         // 64
    float* bc = bg + 64;              // 64
    float* pg = bc + 64;              // 2*64
    float* pc = pg + 128;             // 2*64

    int tid = threadIdx.x;
    // load W' (16384 floats) + consts
    {
        const float4* src = reinterpret_cast<const float4*>(g_Wp);
        float4* dst = reinterpret_cast<float4*>(Ws);
        for (int i = tid; i < 128 * 128 / 4; i += 256) dst[i] = src[i];
        if (tid < 64) { bg[tid] = b_gate[tid]; bc[tid] = b_cand[tid]; }
        if (tid < 128) { pg[tid] = g_projG[tid]; pc[tid] = g_projC[tid]; }
    }
    __syncthreads();

    int warp = tid >> 5, lane = tid & 31;
    float* myxs = xs + warp * 256;
    int gw = blockIdx.x * 8 + warp;
    int tw = gridDim.x * 8;
    int b = lane >> 4, p = lane & 15;

    for (int n = gw; n < NN; n += tw) {
        // stage x = [s(64) | agg(64)] for both batches into smem
        const float4* srow = reinterpret_cast<const float4*>(state) + ((size_t)b * NN + n) * 16;
        const float4* arow = reinterpret_cast<const float4*>(g_agg) + ((size_t)b * NN + n) * 16;
        float4 sv = srow[p];
        float4 av = arow[p];
        reinterpret_cast<float4*>(myxs + b * 128)[p] = sv;
        reinterpret_cast<float4*>(myxs + b * 128 + 64)[p] = av;
        __syncwarp();

        float acc0[4] = {0.f, 0.f, 0.f, 0.f};   // batch 0, cols 4*lane..4*lane+3
        float acc1[4] = {0.f, 0.f, 0.f, 0.f};   // batch 1
#pragma unroll 8
        for (int k = 0; k < 128; k++) {
            float4 w = reinterpret_cast<const float4*>(Ws + k * 128)[lane];
            float x0 = myxs[k];
            float x1 = myxs[128 + k];
            acc0[0] += w.x * x0; acc0[1] += w.y * x0; acc0[2] += w.z * x0; acc0[3] += w.w * x0;
            acc1[0] += w.x * x1; acc1[1] += w.y * x1; acc1[2] += w.z * x1; acc1[3] += w.w * x1;
        }
        // lane j<16 holds z-pre for cols 4j..4j+3; lane j+16 holds cand-pre for same cols
        float cnd0[4], cnd1[4];
#pragma unroll
        for (int i = 0; i < 4; i++) {
            cnd0[i] = __shfl_xor_sync(0xffffffffu, acc0[i], 16);
            cnd1[i] = __shfl_xor_sync(0xffffffffu, acc1[i], 16);
        }
        int fl = g_flag[n];
        if (lane < 16) {
            int c0 = lane * 4;
#pragma unroll
            for (int bb = 0; bb < 2; bb++) {
                float* accz = bb ? acc1 : acc0;
                float* accc = bb ? cnd1 : cnd0;
                float4 s4 = reinterpret_cast<const float4*>(myxs + bb * 128)[lane];
                float sarr[4] = {s4.x, s4.y, s4.z, s4.w};
                float4 o4;
                float* ov = reinterpret_cast<float*>(&o4);
#pragma unroll
                for (int i = 0; i < 4; i++) {
                    int c = c0 + i;
                    float zp = accz[i] + bg[c] + (fl ? pg[bb * 64 + c] : 0.f);
                    float cp = accc[i] + bc[c] + (fl ? pc[bb * 64 + c] : 0.f);
                    float z = 1.f / (1.f + __expf(-zp));
                    float cd = tanhf(cp);
                    ov[i] = fmaf(z, cd - sarr[i], sarr[i]);
                }
                reinterpret_cast<float4*>(out_ns + ((size_t)(bb * NN + n)) * HH + c0)[0] = o4;
            }
        }
        __syncwarp();
    }
}

// ---------------- K4: readout + policy heads ----------------
__global__ void readout_kernel(const float* __restrict__ ns,   // next_state base
                               const int* __restrict__ efferent_idx,
                               const float* __restrict__ W_dec,
                               const float* __restrict__ b_dec,
                               const float* __restrict__ W_mean,
                               const float* __restrict__ b_mean,
                               const float* __restrict__ W_ls,
                               const float* __restrict__ b_ls,
                               float* __restrict__ out) {
    __shared__ float ro[NB * HH];
    __shared__ float dec[NB * HH];
    int t = threadIdx.x;    // 128 threads
    int b = t >> 6, h = t & 63;
    float sum = 0.f;
    for (int i = 0; i < NEFF; i++) {
        int idx = efferent_idx[i];
        sum += ns[((size_t)b * NN + idx) * HH + h];
    }
    ro[b * HH + h] = sum * (1.f / NEFF);
    __syncthreads();
    float acc = b_dec[h];
    for (int k = 0; k < HH; k++)
        acc += ro[b * HH + k] * W_dec[k * HH + h];
    dec[b * HH + h] = tanhf(acc);
    __syncthreads();
    if (t < NB * NA) {
        int bb = t / NA, a = t % NA;
        float m = b_mean[a], ls = b_ls[a];
        for (int k = 0; k < HH; k++) {
            float d = dec[bb * HH + k];
            m  += d * W_mean[k * NA + a];
            ls += d * W_ls[k * NA + a];
        }
        ls = fminf(fmaxf(ls, -5.f), 2.f);
        out[bb * NA + a] = m;                 // mean
        out[NB * NA + bb * NA + a] = ls;      // log_std
    }
}

// ---------------- launch ----------------
extern "C" void kernel_launch(void* const* d_in, const int* in_sizes, int n_in,
                              void* d_out, int out_size) {
    const float* obs    = (const float*)d_in[0];
    const float* state  = (const float*)d_in[1];
    const float* W_in   = (const float*)d_in[2];
    const float* b_in   = (const float*)d_in[3];
    const float* W_msg  = (const float*)d_in[4];
    const float* W_gate = (const float*)d_in[5];
    const float* b_gate = (const float*)d_in[6];
    const float* W_cand = (const float*)d_in[7];
    const float* b_cand = (const float*)d_in[8];
    const float* W_dec  = (const float*)d_in[9];
    const float* b_dec  = (const float*)d_in[10];
    const float* W_mean = (const float*)d_in[11];
    const float* b_mean = (const float*)d_in[12];
    const float* W_ls   = (const float*)d_in[13];
    const float* b_ls   = (const float*)d_in[14];
    const int* src_idx  = (const int*)d_in[15];
    const int* dst_idx  = (const int*)d_in[16];
    const int* aff_idx  = (const int*)d_in[17];
    const int* eff_idx  = (const int*)d_in[18];
    float* out = (float*)d_out;
    float* out_ns = out + 2 * NB * NA;   // next_state after mean(36) + log_std(36)

    void *aggp = nullptr, *flagp = nullptr;
    cudaGetSymbolAddress(&aggp, g_agg);
    cudaGetSymbolAddress(&flagp, g_flag);
    cudaMemsetAsync(aggp, 0, sizeof(float) * NB * NN * HH);
    cudaMemsetAsync(flagp, 0, sizeof(int) * NN);

    prep_small_kernel<<<1, 128>>>(obs, W_in, b_in, W_gate, W_cand, aff_idx);
    prep_W_kernel<<<128, 128>>>(W_msg, W_gate, W_cand);
    edge_kernel<<<(NE + 7) / 8, 256>>>(state, src_idx, dst_idx);

    size_t smem = (size_t)(128 * 128 + 8 * 256 + 64 + 64 + 128 + 128) * sizeof(float);
    cudaFuncSetAttribute(gemm_kernel, cudaFuncAttributeMaxDynamicSharedMemorySize, (int)smem);
    gemm_kernel<<<296, 256, smem>>>(state, b_gate, b_cand, out_ns);

    readout_kernel<<<1, 128>>>(out_ns, eff_idx, W_dec, b_dec, W_mean, b_mean, W_ls, b_ls, out);
}